// round 13
// baseline (speedup 1.0000x reference)
#include <cuda_runtime.h>
#include <cuda_bf16.h>

// Problem constants
#define BB 8
#define NN 512
#define DD 64
#define EE 32

#define JT 64                 // edge: j's per block (8 warps x 8 j)
#define SS 16                 // i-splits
#define IT (NN / SS)          // 32 i-rows per block
#define BPB (SS * (NN / JT))  // 128 edge blocks per batch b

#define RPB 16                // proj: x-rows per block
#define RPW 4                 // proj: rows per warp

// Scratch (allocation-free rule -> __device__ globals)
__device__ float g_src [BB * NN * EE];        // src[b,n,e]
__device__ float g_dstb[BB * NN * EE];        // dst[b,n,e] + be[e]
__device__ float g_part[BB * NN * SS];        // partial[b,j,s]
__device__ unsigned int g_done[BB];           // monotonic completion counters

// ---- packed fp32 pair helpers (sm_103a FADD2/FFMA2 via PTX f32x2) ----------
union F2U { unsigned long long u; float2 f; };

__device__ __forceinline__ unsigned long long add2(unsigned long long a,
                                                   unsigned long long b) {
    unsigned long long r;
    asm("add.rn.f32x2 %0, %1, %2;" : "=l"(r) : "l"(a), "l"(b));
    return r;
}
__device__ __forceinline__ unsigned long long fma2(unsigned long long a,
                                                   unsigned long long b,
                                                   unsigned long long c) {
    unsigned long long r;
    asm("fma.rn.f32x2 %0, %1, %2, %3;" : "=l"(r) : "l"(a), "l"(b), "l"(c));
    return r;
}

// ---------------------------------------------------------------------------
// Kernel 1 (R4 exact + PDL trigger): src = x @ We[:D], dstb = x @ We[D:] + be
// ---------------------------------------------------------------------------
__global__ __launch_bounds__(256) void proj_kernel(
    const float* __restrict__ x,
    const float* __restrict__ We,
    const float* __restrict__ be)
{
    const int row0 = blockIdx.x * RPB;
    __shared__ float xs [RPB][DD];              // 4 KB
    __shared__ float Wsh[2 * DD][EE];           // 16 KB

    const int tid = threadIdx.x;
    #pragma unroll
    for (int k = 0; k < 4; k++)
        ((float4*)Wsh)[k * 256 + tid] = ((const float4*)We)[k * 256 + tid];
    ((float4*)xs)[tid] = ((const float4*)(x + row0 * DD))[tid];
    __syncthreads();

    const int lane = tid & 31;                  // = e
    const int w    = tid >> 5;
    const int half = w >> 2;                    // 0 = src, 1 = dst
    const int r0   = (w & 3) * RPW;

    const float* Wh = &Wsh[half * DD][0];
    const float bias = half ? be[lane] : 0.0f;

    float acc[RPW];
    #pragma unroll
    for (int r = 0; r < RPW; r++) acc[r] = bias;

    #pragma unroll
    for (int d4 = 0; d4 < DD; d4 += 4) {
        float4 xv[RPW];
        #pragma unroll
        for (int r = 0; r < RPW; r++)
            xv[r] = *(const float4*)&xs[r0 + r][d4];
        #pragma unroll
        for (int k = 0; k < 4; k++) {
            float wv = Wh[(d4 + k) * EE + lane];
            #pragma unroll
            for (int r = 0; r < RPW; r++)
                acc[r] = fmaf((&xv[r].x)[k], wv, acc[r]);
        }
    }

    float* dst = half ? g_dstb : g_src;
    #pragma unroll
    for (int r = 0; r < RPW; r++)
        dst[(row0 + r0 + r) * EE + lane] = acc[r];

    // PDL: writes done -> signal dependent (edge) kernel
    __threadfence();
    cudaTriggerProgrammaticLaunchCompletion();
}

// ---------------------------------------------------------------------------
// Kernel 2: edge reduce (e-packed f32x2, quad smem) + last-block final reduce.
// PDL: stages Wr into registers BEFORE cudaGridDependencySynchronize(),
// overlapping proj's execution; src/dstb staged after the sync.
// Grid (8,8,16) = 1024 blocks, 256 threads.
// ---------------------------------------------------------------------------
__global__ __launch_bounds__(256) void edge_reduce_kernel(
    const float* __restrict__ Wr,
    const float* __restrict__ br,
    float* __restrict__ part,
    float* __restrict__ out)
{
    const int jb = blockIdx.x;
    const int b  = blockIdx.y;
    const int s  = blockIdx.z;
    const int tid  = threadIdx.x;
    const int lane = tid & 31;
    const int w    = tid >> 5;                  // warp 0..7
    const int le   = lane & 15;                 // e-pair index (e = 2*le)
    const int jg   = lane >> 4;                 // j-group within warp

    __shared__ float4 q_sh [IT * 16];           // 8 KB: (s0,s1,w0,w1) quads
    __shared__ float  dst_sh[JT * EE];          // 8 KB
    __shared__ int    s_last;

    // --- PDL prologue: Wr load is independent of proj -> issue it now ---
    const float4 wv4 = ((const float4*)(Wr + s * IT * EE))[tid];
    const float brv  = br[0];

    cudaGridDependencySynchronize();            // wait for proj's writes

    // stage: dst (2 float4/thread); src combined with pre-loaded Wr into quads
    {
        const float4* dst_g = (const float4*)(g_dstb + (b * NN + jb * JT) * EE);
        const float4* src_g = (const float4*)(g_src  + (b * NN + s  * IT) * EE);
        #pragma unroll
        for (int k = 0; k < 2; k++)
            ((float4*)dst_sh)[k * 256 + tid] = dst_g[k * 256 + tid];

        float4 sv = src_g[tid];                 // 256 float4 = IT*EE/4
        const int row = tid >> 3, c8 = tid & 7;
        q_sh[row * 16 + c8 * 2    ] = make_float4(sv.x, sv.y, wv4.x, wv4.y);
        q_sh[row * 16 + c8 * 2 + 1] = make_float4(sv.z, sv.w, wv4.z, wv4.w);
    }
    __syncthreads();

    const int jl0 = w * 8 + jg * 4;             // this thread's first j (of 4)
    F2U dreg2[4], acc2[4];
    #pragma unroll
    for (int r = 0; r < 4; r++) {
        dreg2[r].f = *(const float2*)&dst_sh[(jl0 + r) * EE + 2 * le];
        acc2[r].u  = 0ull;
    }

    // inner loop: 1 LDS.128 + 16 pipe issues per i (double-buffered)
    float4 cur = q_sh[le];
    #pragma unroll 4
    for (int i = 0; i < IT; i++) {
        const float4 nxt = (i + 1 < IT) ? q_sh[(i + 1) * 16 + le] : cur;
        F2U sv2, wv2;
        sv2.f.x = cur.x; sv2.f.y = cur.y;
        wv2.f.x = cur.z; wv2.f.y = cur.w;
        #pragma unroll
        for (int r = 0; r < 4; r++) {
            F2U t; t.u = add2(sv2.u, dreg2[r].u);       // FADD2
            t.f.x = fmaxf(t.f.x, 0.0f);                 // FMNMX (alu pipe)
            t.f.y = fmaxf(t.f.y, 0.0f);
            acc2[r].u = fma2(t.u, wv2.u, acc2[r].u);    // FFMA2
        }
        cur = nxt;
    }

    // collapse e-pair, reduce over the 16 lanes of each half-warp
    float acc[4];
    #pragma unroll
    for (int r = 0; r < 4; r++) {
        acc[r] = acc2[r].f.x + acc2[r].f.y;
        #pragma unroll
        for (int off = 8; off; off >>= 1)
            acc[r] += __shfl_xor_sync(0xFFFFFFFFu, acc[r], off);
    }

    if (le == 0) {                              // lanes 0 and 16 write
        const int j = jb * JT + jl0;
        #pragma unroll
        for (int r = 0; r < 4; r++)
            part[(b * NN + j + r) * SS + s] = acc[r];
    }

    // ---- completion: the 128th block of this b does b's final reduce ----
    __threadfence();
    __syncthreads();
    if (tid == 0) {
        unsigned int cnt = atomicAdd(&g_done[b], 1u) + 1u;   // monotonic
        s_last = ((cnt & (BPB - 1u)) == 0u);    // 128 blocks per b per launch
    }
    __syncthreads();
    if (!s_last) return;
    __threadfence();                            // acquire partials

    #pragma unroll
    for (int k = 0; k < 2; k++) {
        const int j = k * 256 + tid;            // 0..511
        const float4* p4 = (const float4*)(part + (b * NN + j) * SS);
        float4 a0 = p4[0], a1 = p4[1], a2 = p4[2], a3 = p4[3];
        float r0 = (a0.x + a0.y) + (a0.z + a0.w);
        float r1 = (a1.x + a1.y) + (a1.z + a1.w);
        float r2 = (a2.x + a2.y) + (a2.z + a2.w);
        float r3 = (a3.x + a3.y) + (a3.z + a3.w);
        out[b * NN + j] = (r0 + r1) + (r2 + r3) + brv;
    }
}

// ---------------------------------------------------------------------------
// launch: proj, then edge with PDL (programmatic stream serialization)
// ---------------------------------------------------------------------------
extern "C" void kernel_launch(void* const* d_in, const int* in_sizes, int n_in,
                              void* d_out, int out_size)
{
    const float* x  = (const float*)d_in[0];   // (8,512,64)
    const float* We = (const float*)d_in[1];   // (128,32)
    const float* be = (const float*)d_in[2];   // (32,)
    const float* Wr = (const float*)d_in[3];   // (16384,1)
    const float* br = (const float*)d_in[4];   // (1,)
    float* out = (float*)d_out;                // (8,512,1)

    float* partp;
    cudaGetSymbolAddress((void**)&partp, g_part);

    proj_kernel<<<BB * NN / RPB, 256>>>(x, We, be);

    cudaLaunchConfig_t cfg = {};
    cfg.gridDim  = dim3(NN / JT, BB, SS);      // (8,8,16) = 1024 blocks
    cfg.blockDim = dim3(256, 1, 1);
    cudaLaunchAttribute attrs[1];
    attrs[0].id = cudaLaunchAttributeProgrammaticStreamSerialization;
    attrs[0].val.programmaticStreamSerializationAllowed = 1;
    cfg.attrs = attrs;
    cfg.numAttrs = 1;
    cudaLaunchKernelEx(&cfg, edge_reduce_kernel, Wr, br, partp, out);
}

// round 14
// speedup vs baseline: 1.0017x; 1.0017x over previous
#include <cuda_runtime.h>
#include <cuda_bf16.h>

// Problem constants
#define BB 8
#define NN 512
#define DD 64
#define EE 32

#define JT 64                 // edge: j's per block (8 warps x 8 j)
#define SS 16                 // i-splits
#define IT (NN / SS)          // 32 i-rows per block
#define BPB (SS * (NN / JT))  // 128 edge blocks per batch b

#define RPB 16                // proj: x-rows per block
#define RPW 4                 // proj: rows per warp

// Scratch (allocation-free rule -> __device__ globals)
__device__ float g_src [BB * NN * EE];        // src[b,n,e]
__device__ float g_dstb[BB * NN * EE];        // dst[b,n,e] + be[e]
__device__ float g_part[BB * NN * SS];        // partial[b,j,s]
__device__ unsigned int g_done[BB];           // monotonic completion counters

// ---- packed fp32 pair helpers (sm_103a FADD2/FFMA2 via PTX f32x2) ----------
union F2U { unsigned long long u; float2 f; };

__device__ __forceinline__ unsigned long long add2(unsigned long long a,
                                                   unsigned long long b) {
    unsigned long long r;
    asm("add.rn.f32x2 %0, %1, %2;" : "=l"(r) : "l"(a), "l"(b));
    return r;
}
__device__ __forceinline__ unsigned long long fma2(unsigned long long a,
                                                   unsigned long long b,
                                                   unsigned long long c) {
    unsigned long long r;
    asm("fma.rn.f32x2 %0, %1, %2, %3;" : "=l"(r) : "l"(a), "l"(b), "l"(c));
    return r;
}

// ---------------------------------------------------------------------------
// Kernel 1 (R4 exact): src = x @ We[:D], dstb = x @ We[D:] + be
// ---------------------------------------------------------------------------
__global__ __launch_bounds__(256) void proj_kernel(
    const float* __restrict__ x,
    const float* __restrict__ We,
    const float* __restrict__ be)
{
    const int row0 = blockIdx.x * RPB;
    __shared__ float xs [RPB][DD];              // 4 KB
    __shared__ float Wsh[2 * DD][EE];           // 16 KB

    const int tid = threadIdx.x;
    #pragma unroll
    for (int k = 0; k < 4; k++)
        ((float4*)Wsh)[k * 256 + tid] = ((const float4*)We)[k * 256 + tid];
    ((float4*)xs)[tid] = ((const float4*)(x + row0 * DD))[tid];
    __syncthreads();

    const int lane = tid & 31;                  // = e
    const int w    = tid >> 5;
    const int half = w >> 2;                    // 0 = src, 1 = dst
    const int r0   = (w & 3) * RPW;

    const float* Wh = &Wsh[half * DD][0];
    const float bias = half ? be[lane] : 0.0f;

    float acc[RPW];
    #pragma unroll
    for (int r = 0; r < RPW; r++) acc[r] = bias;

    #pragma unroll
    for (int d4 = 0; d4 < DD; d4 += 4) {
        float4 xv[RPW];
        #pragma unroll
        for (int r = 0; r < RPW; r++)
            xv[r] = *(const float4*)&xs[r0 + r][d4];
        #pragma unroll
        for (int k = 0; k < 4; k++) {
            float wv = Wh[(d4 + k) * EE + lane];
            #pragma unroll
            for (int r = 0; r < RPW; r++)
                acc[r] = fmaf((&xv[r].x)[k], wv, acc[r]);
        }
    }

    float* dst = half ? g_dstb : g_src;
    #pragma unroll
    for (int r = 0; r < RPW; r++)
        dst[(row0 + r0 + r) * EE + lane] = acc[r];
}

// ---------------------------------------------------------------------------
// Kernel 2: edge reduce (e-packed f32x2, quad smem, 4-deep LDS pipeline)
// + last-block-per-b fused final reduce. Grid (8,8,16) = 1024 blocks.
// ---------------------------------------------------------------------------
__global__ __launch_bounds__(256) void edge_reduce_kernel(
    const float* __restrict__ Wr,
    const float* __restrict__ br,
    float* __restrict__ part,
    float* __restrict__ out)
{
    const int jb = blockIdx.x;
    const int b  = blockIdx.y;
    const int s  = blockIdx.z;
    const int tid  = threadIdx.x;
    const int lane = tid & 31;
    const int w    = tid >> 5;                  // warp 0..7
    const int le   = lane & 15;                 // e-pair index (e = 2*le)
    const int jg   = lane >> 4;                 // j-group within warp

    __shared__ float4 q_sh [IT * 16];           // 8 KB: (s0,s1,w0,w1) quads
    __shared__ float  dst_sh[JT * EE];          // 8 KB
    __shared__ int    s_last;

    // stage: dst (2 float4/thread); src+Wr interleaved into quads (1/thread)
    {
        const float4* dst_g = (const float4*)(g_dstb + (b * NN + jb * JT) * EE);
        const float4* src_g = (const float4*)(g_src  + (b * NN + s  * IT) * EE);
        const float4* wr_g  = (const float4*)(Wr + s * IT * EE);
        #pragma unroll
        for (int k = 0; k < 2; k++)
            ((float4*)dst_sh)[k * 256 + tid] = dst_g[k * 256 + tid];

        float4 sv = src_g[tid];                 // 256 float4 = IT*EE/4
        float4 wv = wr_g [tid];
        const int row = tid >> 3, c8 = tid & 7;
        q_sh[row * 16 + c8 * 2    ] = make_float4(sv.x, sv.y, wv.x, wv.y);
        q_sh[row * 16 + c8 * 2 + 1] = make_float4(sv.z, sv.w, wv.z, wv.w);
    }
    __syncthreads();

    const int jl0 = w * 8 + jg * 4;             // this thread's first j (of 4)
    F2U dreg2[4], acc2[4];
    #pragma unroll
    for (int r = 0; r < 4; r++) {
        dreg2[r].f = *(const float2*)&dst_sh[(jl0 + r) * EE + 2 * le];
        acc2[r].u  = 0ull;
    }

    // 4-deep software pipeline: 4 independent LDS.128 in flight per chunk
    float4 buf[4];
    #pragma unroll
    for (int u = 0; u < 4; u++) buf[u] = q_sh[u * 16 + le];

    #pragma unroll 2
    for (int ic = 0; ic < IT; ic += 4) {
        float4 nbuf[4];
        const bool more = (ic + 4 < IT);
        #pragma unroll
        for (int u = 0; u < 4; u++)
            nbuf[u] = more ? q_sh[(ic + 4 + u) * 16 + le] : buf[u];

        #pragma unroll
        for (int u = 0; u < 4; u++) {
            F2U sv2, wv2;
            sv2.f.x = buf[u].x; sv2.f.y = buf[u].y;
            wv2.f.x = buf[u].z; wv2.f.y = buf[u].w;
            #pragma unroll
            for (int r = 0; r < 4; r++) {
                F2U t; t.u = add2(sv2.u, dreg2[r].u);       // FADD2
                t.f.x = fmaxf(t.f.x, 0.0f);                 // FMNMX (alu pipe)
                t.f.y = fmaxf(t.f.y, 0.0f);
                acc2[r].u = fma2(t.u, wv2.u, acc2[r].u);    // FFMA2
            }
        }
        #pragma unroll
        for (int u = 0; u < 4; u++) buf[u] = nbuf[u];
    }

    // collapse e-pair, reduce over the 16 lanes of each half-warp
    float acc[4];
    #pragma unroll
    for (int r = 0; r < 4; r++) {
        acc[r] = acc2[r].f.x + acc2[r].f.y;
        #pragma unroll
        for (int off = 8; off; off >>= 1)
            acc[r] += __shfl_xor_sync(0xFFFFFFFFu, acc[r], off);
    }

    if (le == 0) {                              // lanes 0 and 16 write
        const int j = jb * JT + jl0;
        #pragma unroll
        for (int r = 0; r < 4; r++)
            part[(b * NN + j + r) * SS + s] = acc[r];
    }

    // ---- completion: the 128th block of this b does b's final reduce ----
    __threadfence();
    __syncthreads();
    if (tid == 0) {
        unsigned int cnt = atomicAdd(&g_done[b], 1u) + 1u;   // monotonic
        s_last = ((cnt & (BPB - 1u)) == 0u);    // 128 blocks per b per launch
    }
    __syncthreads();
    if (!s_last) return;
    __threadfence();                            // acquire partials

    const float brv = br[0];
    #pragma unroll
    for (int k = 0; k < 2; k++) {
        const int j = k * 256 + tid;            // 0..511
        const float4* p4 = (const float4*)(part + (b * NN + j) * SS);
        float4 a0 = p4[0], a1 = p4[1], a2 = p4[2], a3 = p4[3];
        float r0 = (a0.x + a0.y) + (a0.z + a0.w);
        float r1 = (a1.x + a1.y) + (a1.z + a1.w);
        float r2 = (a2.x + a2.y) + (a2.z + a2.w);
        float r3 = (a3.x + a3.y) + (a3.z + a3.w);
        out[b * NN + j] = (r0 + r1) + (r2 + r3) + brv;
    }
}

// ---------------------------------------------------------------------------
// launch: TWO kernels (no PDL — measured neutral)
// ---------------------------------------------------------------------------
extern "C" void kernel_launch(void* const* d_in, const int* in_sizes, int n_in,
                              void* d_out, int out_size)
{
    const float* x  = (const float*)d_in[0];   // (8,512,64)
    const float* We = (const float*)d_in[1];   // (128,32)
    const float* be = (const float*)d_in[2];   // (32,)
    const float* Wr = (const float*)d_in[3];   // (16384,1)
    const float* br = (const float*)d_in[4];   // (1,)
    float* out = (float*)d_out;                // (8,512,1)

    float* partp;
    cudaGetSymbolAddress((void**)&partp, g_part);

    proj_kernel<<<BB * NN / RPB, 256>>>(x, We, be);

    dim3 grid(NN / JT, BB, SS);                // (8,8,16) = 1024 blocks
    edge_reduce_kernel<<<grid, 256>>>(Wr, br, partp, out);
}

// round 15
// speedup vs baseline: 1.1385x; 1.1366x over previous
#include <cuda_runtime.h>
#include <cuda_bf16.h>

// Problem constants
#define BB 8
#define NN 512
#define DD 64
#define EE 32

#define JT 64                 // edge: j's per block (8 warps x 8 j)
#define SS 16                 // i-splits
#define IT (NN / SS)          // 32 i-rows per block

#define RPB 16                // proj: x-rows per block
#define RPW 4                 // proj: rows per warp

// Scratch (allocation-free rule -> __device__ globals)
__device__ float g_src [BB * NN * EE];        // src[b,n,e]
__device__ float g_dstb[BB * NN * EE];        // dst[b,n,e] + be[e]

// ---- packed fp32 pair helpers (sm_103a FADD2/FFMA2 via PTX f32x2) ----------
union F2U { unsigned long long u; float2 f; };

__device__ __forceinline__ unsigned long long add2(unsigned long long a,
                                                   unsigned long long b) {
    unsigned long long r;
    asm("add.rn.f32x2 %0, %1, %2;" : "=l"(r) : "l"(a), "l"(b));
    return r;
}
__device__ __forceinline__ unsigned long long fma2(unsigned long long a,
                                                   unsigned long long b,
                                                   unsigned long long c) {
    unsigned long long r;
    asm("fma.rn.f32x2 %0, %1, %2, %3;" : "=l"(r) : "l"(a), "l"(b), "l"(c));
    return r;
}

// ---------------------------------------------------------------------------
// Kernel 1 (R4-exact body): src = x @ We[:D], dstb = x @ We[D:] + be
// Blocks 0..15 additionally initialize out[] = br (proj precedes edge in
// stream order, so edge's atomics never race this).
// ---------------------------------------------------------------------------
__global__ __launch_bounds__(256) void proj_kernel(
    const float* __restrict__ x,
    const float* __restrict__ We,
    const float* __restrict__ be,
    const float* __restrict__ br,
    float* __restrict__ out)
{
    const int row0 = blockIdx.x * RPB;
    __shared__ float xs [RPB][DD];              // 4 KB
    __shared__ float Wsh[2 * DD][EE];           // 16 KB

    const int tid = threadIdx.x;

    if (blockIdx.x < 16)                        // out init: 16*256 = 4096
        out[blockIdx.x * 256 + tid] = br[0];

    #pragma unroll
    for (int k = 0; k < 4; k++)
        ((float4*)Wsh)[k * 256 + tid] = ((const float4*)We)[k * 256 + tid];
    ((float4*)xs)[tid] = ((const float4*)(x + row0 * DD))[tid];
    __syncthreads();

    const int lane = tid & 31;                  // = e
    const int w    = tid >> 5;
    const int half = w >> 2;                    // 0 = src, 1 = dst
    const int r0   = (w & 3) * RPW;

    const float* Wh = &Wsh[half * DD][0];
    const float bias = half ? be[lane] : 0.0f;

    float acc[RPW];
    #pragma unroll
    for (int r = 0; r < RPW; r++) acc[r] = bias;

    #pragma unroll
    for (int d4 = 0; d4 < DD; d4 += 4) {
        float4 xv[RPW];
        #pragma unroll
        for (int r = 0; r < RPW; r++)
            xv[r] = *(const float4*)&xs[r0 + r][d4];
        #pragma unroll
        for (int k = 0; k < 4; k++) {
            float wv = Wh[(d4 + k) * EE + lane];
            #pragma unroll
            for (int r = 0; r < RPW; r++)
                acc[r] = fmaf((&xv[r].x)[k], wv, acc[r]);
        }
    }

    float* dst = half ? g_dstb : g_src;
    #pragma unroll
    for (int r = 0; r < RPW; r++)
        dst[(row0 + r0 + r) * EE + lane] = acc[r];
}

// ---------------------------------------------------------------------------
// Kernel 2 (R11-exact body): edge reduce, e-packed f32x2, quad smem.
// Ends with direct atomicAdd into out (no partial buffer, no counter, no tail).
// Grid (8,8,16) = 1024 blocks, 256 threads.
// ---------------------------------------------------------------------------
__global__ __launch_bounds__(256) void edge_reduce_kernel(
    const float* __restrict__ Wr,
    float* __restrict__ out)
{
    const int jb = blockIdx.x;
    const int b  = blockIdx.y;
    const int s  = blockIdx.z;
    const int tid  = threadIdx.x;
    const int lane = tid & 31;
    const int w    = tid >> 5;                  // warp 0..7
    const int le   = lane & 15;                 // e-pair index (e = 2*le)
    const int jg   = lane >> 4;                 // j-group within warp

    __shared__ float4 q_sh [IT * 16];           // 8 KB: (s0,s1,w0,w1) quads
    __shared__ float  dst_sh[JT * EE];          // 8 KB

    // stage: dst (2 float4/thread); src+Wr interleaved into quads (1/thread)
    {
        const float4* dst_g = (const float4*)(g_dstb + (b * NN + jb * JT) * EE);
        const float4* src_g = (const float4*)(g_src  + (b * NN + s  * IT) * EE);
        const float4* wr_g  = (const float4*)(Wr + s * IT * EE);
        #pragma unroll
        for (int k = 0; k < 2; k++)
            ((float4*)dst_sh)[k * 256 + tid] = dst_g[k * 256 + tid];

        float4 sv = src_g[tid];                 // 256 float4 = IT*EE/4
        float4 wv = wr_g [tid];
        const int row = tid >> 3, c8 = tid & 7;
        q_sh[row * 16 + c8 * 2    ] = make_float4(sv.x, sv.y, wv.x, wv.y);
        q_sh[row * 16 + c8 * 2 + 1] = make_float4(sv.z, sv.w, wv.z, wv.w);
    }
    __syncthreads();

    const int jl0 = w * 8 + jg * 4;             // this thread's first j (of 4)
    F2U dreg2[4], acc2[4];
    #pragma unroll
    for (int r = 0; r < 4; r++) {
        dreg2[r].f = *(const float2*)&dst_sh[(jl0 + r) * EE + 2 * le];
        acc2[r].u  = 0ull;
    }

    // inner loop: 1 LDS.128 + 16 pipe issues per i (double-buffered)
    float4 cur = q_sh[le];
    #pragma unroll 4
    for (int i = 0; i < IT; i++) {
        const float4 nxt = (i + 1 < IT) ? q_sh[(i + 1) * 16 + le] : cur;
        F2U sv2, wv2;
        sv2.f.x = cur.x; sv2.f.y = cur.y;
        wv2.f.x = cur.z; wv2.f.y = cur.w;
        #pragma unroll
        for (int r = 0; r < 4; r++) {
            F2U t; t.u = add2(sv2.u, dreg2[r].u);       // FADD2
            t.f.x = fmaxf(t.f.x, 0.0f);                 // FMNMX (alu pipe)
            t.f.y = fmaxf(t.f.y, 0.0f);
            acc2[r].u = fma2(t.u, wv2.u, acc2[r].u);    // FFMA2
        }
        cur = nxt;
    }

    // collapse e-pair, reduce over the 16 lanes of each half-warp
    float acc[4];
    #pragma unroll
    for (int r = 0; r < 4; r++) {
        acc[r] = acc2[r].f.x + acc2[r].f.y;
        #pragma unroll
        for (int off = 8; off; off >>= 1)
            acc[r] += __shfl_xor_sync(0xFFFFFFFFu, acc[r], off);
    }

    if (le == 0) {                              // lanes 0 and 16: 8 atomics/warp
        const int j = jb * JT + jl0;
        #pragma unroll
        for (int r = 0; r < 4; r++)
            atomicAdd(&out[b * NN + j + r], acc[r]);
    }
}

// ---------------------------------------------------------------------------
// launch: TWO kernels, no scratch round-trip for the output
// ---------------------------------------------------------------------------
extern "C" void kernel_launch(void* const* d_in, const int* in_sizes, int n_in,
                              void* d_out, int out_size)
{
    const float* x  = (const float*)d_in[0];   // (8,512,64)
    const float* We = (const float*)d_in[1];   // (128,32)
    const float* be = (const float*)d_in[2];   // (32,)
    const float* Wr = (const float*)d_in[3];   // (16384,1)
    const float* br = (const float*)d_in[4];   // (1,)
    float* out = (float*)d_out;                // (8,512,1)

    proj_kernel<<<BB * NN / RPB, 256>>>(x, We, be, br, out);

    dim3 grid(NN / JT, BB, SS);                // (8,8,16) = 1024 blocks
    edge_reduce_kernel<<<grid, 256>>>(Wr, out);
}